// round 13
// baseline (speedup 1.0000x reference)
#include <cuda_runtime.h>
#include <mma.h>
#include <math.h>
#include <stdint.h>

using namespace nvcuda;

#define TPIf 6.2831853071795864769f

constexpr int Bsz  = 16384;
constexpr int S    = 15;
constexpr int MID  = 240;
constexpr int EMB  = 6;
constexpr int OUTC = 48;
constexpr int BT   = 4;
constexpr int NT   = 256;

constexpr int XROW   = 36;
constexpr int XPANEL = 48*XROW + 4;
constexpr int SGROW  = 36;
constexpr int HSTR   = 3876;

constexpr int SC_SUM  = 0;
constexpr int SC_SQ   = 960;
constexpr int SC_R2S  = 1920;
constexpr int SC_R2Q  = 1968;
constexpr int SC_PAR  = 0;
constexpr int SC_SIZE = 3648;

__device__ __forceinline__ int h1off(int b, int c) {
    return b*HSTR + c*16 + 4*((c/30) & 7);
}

__device__ __forceinline__ float tf32r(float x) {
    uint32_t r;
    asm("cvt.rna.tf32.f32 %0, %1;" : "=r"(r) : "f"(x));
    return __uint_as_float(r);
}

// ===== weight scratch (prep-built) =====
// conv1 W fragments: [mt(15)][kt(96)][r(16)][k(8)] tf32-rounded hi/lo
__device__ __align__(16) float g_w1hi[184320];
__device__ __align__(16) float g_w1lo[184320];
__device__ float g_w2p [6*240*16];
__device__ float g_dw1p[6*240*16];
__device__ float g_dw2p[48*240*8];
__device__ float g_nw1p[240*16];
__device__ float g_nb1p[240*16];
__device__ float g_dnwp[240*16];
__device__ float g_dnbp[240*16];

constexpr int NA = 2*184320;
constexpr int N2 = 6*240*16, N3 = 6*240*16, N4 = 48*240*8, N5 = 4*240*16;

__global__ void prep_kernel(const float* __restrict__ w1, const float* __restrict__ w2,
                            const float* __restrict__ dw1, const float* __restrict__ dw2,
                            const float* __restrict__ nw1, const float* __restrict__ nb1,
                            const float* __restrict__ dnw, const float* __restrict__ dnb)
{
    int i = blockIdx.x*blockDim.x + threadIdx.x;
    if (i < NA) {
        int term = i / 184320;
        int j = i - term*184320;
        int kk = j & 7;
        int r  = (j >> 3) & 15;
        int ktmt = j >> 7;
        int kt = ktmt % 96, mt = ktmt / 96;
        int m = mt*16 + r;
        int K = kt*8 + kk;
        int c = K >> 4, kh = K & 15;
        float w = (kh < 15) ? w1[(m*48 + c)*15 + kh] : 0.f;
        float hi = tf32r(w);
        float val = term ? tf32r(w - hi) : hi;
        if (term) g_w1lo[j] = val; else g_w1hi[j] = val;
    } else if (i < NA+N2) {
        int j = i - NA; int k = j & 15, ec = j >> 4;
        g_w2p[j] = (k < 15) ? w2[ec*15 + k] : 0.f;
    } else if (i < NA+N2+N3) {
        int j = i - NA - N2; int k = j & 15, em = j >> 4;
        int e = em / 240, m = em % 240;
        g_dw1p[j] = (k < 15) ? dw1[(m*6 + e)*15 + k] : 0.f;
    } else if (i < NA+N2+N3+N4) {
        int j = i - NA - N2 - N3; int k = j & 7, oc = j >> 3;
        g_dw2p[j] = dw2[oc*15 + k];
    } else if (i < NA+N2+N3+N4+N5) {
        int j = i - NA - N2 - N3 - N4;
        int tab = j / 3840, idx = j % 3840;
        int row = idx >> 4, col = idx & 15;
        float v = 0.f;
        if (col < 15) {
            const float* src = (tab == 0) ? nw1 : (tab == 1) ? nb1
                             : (tab == 2) ? dnw : dnb;
            v = src[row*15 + col];
        }
        float* dst = (tab == 0) ? g_nw1p : (tab == 1) ? g_nb1p
                   : (tab == 2) ? g_dnwp : g_dnbp;
        dst[idx] = v;
    }
}

struct Smem {
    float xpad[BT*XPANEL];       // 6928
    float h1[BT*HSTR];           // 15504
    float h2[BT*EMB*S];          // 360  <- Bbuf zone starts here (4096 floats)
    float sigp[BT*EMB*SGROW];    // 864
    float scratch[SC_SIZE];      // 3648
    float ctab[15], stab[15];
    float mean[BT], rstd[BT];
};

__device__ __forceinline__ void conv225(float (&acc)[15], const float (&xv)[32],
                                        const float (&w)[16])
{
    #pragma unroll
    for (int k = 0; k < 15; ++k) {
        #pragma unroll
        for (int s = 0; s < 15; ++s)
            acc[s] = fmaf(w[k], xv[k+s], acc[s]);
    }
}
__device__ __forceinline__ void ldxv32(float (&xv)[32], const float* p) {
    const float4* q = (const float4*)p;
    #pragma unroll
    for (int j = 0; j < 8; ++j) {
        float4 v = q[j];
        xv[4*j+0]=v.x; xv[4*j+1]=v.y; xv[4*j+2]=v.z; xv[4*j+3]=v.w;
    }
}
__device__ __forceinline__ void ldw16g(float (&w)[16], const float* __restrict__ p) {
    const float4* q = (const float4*)p;
    #pragma unroll
    for (int j = 0; j < 4; ++j) {
        float4 v = __ldg(q + j);
        w[4*j+0]=v.x; w[4*j+1]=v.y; w[4*j+2]=v.z; w[4*j+3]=v.w;
    }
}
__device__ __forceinline__ void ldw8g(float (&w)[8], const float* __restrict__ p) {
    const float4* q = (const float4*)p;
    #pragma unroll
    for (int j = 0; j < 2; ++j) {
        float4 v = __ldg(q + j);
        w[4*j+0]=v.x; w[4*j+1]=v.y; w[4*j+2]=v.z; w[4*j+3]=v.w;
    }
}

typedef wmma::fragment<wmma::matrix_a, 16, 16, 8, wmma::precision::tf32, wmma::row_major> FragA;
typedef wmma::fragment<wmma::matrix_b, 16, 16, 8, wmma::precision::tf32, wmma::row_major> FragB;
typedef wmma::fragment<wmma::accumulator, 16, 16, 8, float> FragC;

__global__ void __launch_bounds__(NT, 2)
pae_kernel(const float* __restrict__ x,
           const float* __restrict__ b1,
           const float* __restrict__ b2,
           const float* __restrict__ fcw, const float* __restrict__ fcb,
           const float* __restrict__ db1,
           const float* __restrict__ db2,
           float* __restrict__ out)
{
    extern __shared__ float sm_raw[];
    Smem& sm = *reinterpret_cast<Smem*>(sm_raw);
    const int t  = threadIdx.x;
    const int wid = t >> 5;
    const int b0 = blockIdx.x * BT;

    // ---- phase 0: twiddles, zero x pads, load x ----
    for (int i = t; i < BT*XPANEL; i += NT) sm.xpad[i] = 0.f;
    if (t < 15) {
        float s_, c_;
        sincosf(TPIf * (float)t / 15.f, &s_, &c_);
        sm.ctab[t] = c_;
        sm.stab[t] = -s_;
    }
    __syncthreads();
    for (int i = t; i < BT*720; i += NT) {
        int b = i / 720, r = i - b*720;
        int c = r / 15,  s = r - c*15;
        sm.xpad[b*XPANEL + c*XROW + 7 + s] = x[(size_t)(b0+b)*720 + r];
    }
    __syncthreads();

    // ---- phase 1: conv1 via wmma tf32 (3xTF32 split) ----
    // Bbuf zone: 4096 floats overlaid on h2+sigp+scratch-head (dead during conv1)
    float* bbase = sm.h2;

    #pragma unroll 1
    for (int pass = 0; pass < 2; ++pass) {
        const int  mt  = (pass == 0) ? wid : 8 + wid;
        const bool act = (pass == 0) || (wid < 7);
        FragC acc[4];
        #pragma unroll
        for (int nt = 0; nt < 4; ++nt) wmma::fill_fragment(acc[nt], 0.f);

        #pragma unroll 1
        for (int c = 0; c < 48; ++c) {
            float* buf = bbase + (c & 1)*2048;   // hi at +0, lo at +1024
            for (int i = t; i < 1024; i += NT) {
                int kk = i >> 6, n = i & 63;
                int b = n >> 4, s = n & 15;
                float v = 0.f;
                if (kk < 15 && s < 15) v = sm.xpad[b*XPANEL + c*XROW + kk + s];
                float hi = tf32r(v);
                buf[i]        = hi;
                buf[1024 + i] = tf32r(v - hi);
            }
            __syncthreads();
            if (act) {
                #pragma unroll
                for (int kt2 = 0; kt2 < 2; ++kt2) {
                    FragA ah, al;
                    size_t tile = (size_t)(mt*96 + c*2 + kt2)*128;
                    wmma::load_matrix_sync(ah, g_w1hi + tile, 8);
                    wmma::load_matrix_sync(al, g_w1lo + tile, 8);
                    #pragma unroll
                    for (int nt = 0; nt < 4; ++nt) {
                        FragB bh, bl;
                        wmma::load_matrix_sync(bh, buf + kt2*512 + nt*16, 64);
                        wmma::load_matrix_sync(bl, buf + 1024 + kt2*512 + nt*16, 64);
                        wmma::mma_sync(acc[nt], ah, bh, acc[nt]);
                        wmma::mma_sync(acc[nt], ah, bl, acc[nt]);
                        wmma::mma_sync(acc[nt], al, bh, acc[nt]);
                    }
                }
            }
        }
        __syncthreads();             // all MMAs done; staging may reuse bbase
        if (act) {
            float* stg = bbase + wid*256;
            int lane = t & 31;
            int r = lane >> 1, s0 = (lane & 1)*8;
            int m = mt*16 + r;
            float bias = b1[m];
            #pragma unroll
            for (int nt = 0; nt < 4; ++nt) {     // nt == sample b
                wmma::store_matrix_sync(stg, acc[nt], 16, wmma::mem_row_major);
                __syncwarp();
                float* h = sm.h1 + h1off(nt, m);
                #pragma unroll
                for (int j = 0; j < 8; ++j) {
                    int s = s0 + j;
                    float v = stg[r*16 + s] + bias;
                    h[s] = (s == 15) ? 0.f : v;
                }
                __syncwarp();
            }
        }
        __syncthreads();
    }

    // re-zero sigp (Bbuf trashed it); LN stage-1 sums over h1 (pad col = 0)
    for (int i = t; i < BT*EMB*SGROW; i += NT) sm.sigp[i] = 0.f;
    if (t < 240) {
        #pragma unroll
        for (int b = 0; b < 4; ++b) {
            const float4* q = (const float4*)(sm.h1 + h1off(b, t));
            float ls = 0.f, lq = 0.f;
            #pragma unroll
            for (int j = 0; j < 4; ++j) {
                float4 v = q[j];
                ls += v.x + v.y + v.z + v.w;
                lq += v.x*v.x + v.y*v.y + v.z*v.z + v.w*v.w;
            }
            sm.scratch[SC_SUM + b*240 + t] = ls;
            sm.scratch[SC_SQ  + b*240 + t] = lq;
        }
    }
    __syncthreads();
    if (t < 48) {
        int b = t & 3, g = t >> 2;
        float s_ = 0.f, q_ = 0.f;
        for (int i = 0; i < 20; ++i) {
            s_ += sm.scratch[SC_SUM + b*240 + g*20 + i];
            q_ += sm.scratch[SC_SQ  + b*240 + g*20 + i];
        }
        sm.scratch[SC_R2S + b*12 + g] = s_;
        sm.scratch[SC_R2Q + b*12 + g] = q_;
    }
    __syncthreads();
    if (t < BT) {
        float s_ = 0.f, q_ = 0.f;
        for (int g = 0; g < 12; ++g) {
            s_ += sm.scratch[SC_R2S + t*12 + g];
            q_ += sm.scratch[SC_R2Q + t*12 + g];
        }
        float mn  = s_ * (1.f/3600.f);
        float var = q_ * (1.f/3600.f) - mn*mn;
        sm.mean[t] = mn;
        sm.rstd[t] = rsqrtf(var + 1e-5f);
    }
    __syncthreads();

    // ---- phase 2: LN1 + ELU ----
    for (int i = t; i < 3840; i += NT) {
        int b  = i / 960;
        int rg = i - b*960;
        int row = rg >> 2, g = rg & 3;
        float* hp = sm.h1 + h1off(b, row) + 4*g;
        float4 h = *(float4*)hp;
        float4 w = *(const float4*)(g_nw1p + row*16 + 4*g);
        float4 bb= *(const float4*)(g_nb1p + row*16 + 4*g);
        float mn = sm.mean[b], rs = sm.rstd[b];
        float v;
        v = (h.x-mn)*rs*w.x + bb.x; h.x = (v > 0.f) ? v : (__expf(v)-1.f);
        v = (h.y-mn)*rs*w.y + bb.y; h.y = (v > 0.f) ? v : (__expf(v)-1.f);
        v = (h.z-mn)*rs*w.z + bb.z; h.z = (v > 0.f) ? v : (__expf(v)-1.f);
        v = (h.w-mn)*rs*w.w + bb.w; h.w = (v > 0.f) ? v : (__expf(v)-1.f);
        *(float4*)hp = h;
    }
    __syncthreads();

    // ---- phase 3: conv2 (240->6), 240 threads, 10 c-groups of 24 ----
    if (t < 240) {
        int e = t / 40, r = t - e*40;
        int cg = r >> 2, b = r & 3;
        int c0 = cg * 24;
        float acc[15];
        #pragma unroll
        for (int s = 0; s < 15; ++s) acc[s] = 0.f;
        const float* wg = g_w2p + ((size_t)e*240 + c0)*16;

        float wa[16], wb_[16];
        ldw16g(wa, wg);
        #pragma unroll 1
        for (int ci = 0; ci < 24; ci += 2) {
            ldw16g(wb_, wg + (ci+1)*16);
            {
                float xv[32];
                #pragma unroll
                for (int j = 0; j < 7; ++j)  xv[j] = 0.f;
                #pragma unroll
                for (int j = 23; j < 32; ++j) xv[j] = 0.f;
                const float4* q = (const float4*)(sm.h1 + h1off(b, c0+ci));
                #pragma unroll
                for (int j = 0; j < 4; ++j) {
                    float4 v = q[j];
                    xv[7+4*j]=v.x; xv[8+4*j]=v.y; xv[9+4*j]=v.z; xv[10+4*j]=v.w;
                }
                conv225(acc, xv, wa);
            }
            if (ci+2 < 24) ldw16g(wa, wg + (ci+2)*16);
            {
                float xv[32];
                #pragma unroll
                for (int j = 0; j < 7; ++j)  xv[j] = 0.f;
                #pragma unroll
                for (int j = 23; j < 32; ++j) xv[j] = 0.f;
                const float4* q = (const float4*)(sm.h1 + h1off(b, c0+ci+1));
                #pragma unroll
                for (int j = 0; j < 4; ++j) {
                    float4 v = q[j];
                    xv[7+4*j]=v.x; xv[8+4*j]=v.y; xv[9+4*j]=v.z; xv[10+4*j]=v.w;
                }
                conv225(acc, xv, wb_);
            }
        }
        #pragma unroll
        for (int s = 0; s < 15; ++s) sm.scratch[t*15 + s] = acc[s];
    }
    __syncthreads();
    for (int i = t; i < 360; i += NT) {
        int be = i / 15, s = i - be*15;
        int e = be >> 2, b = be & 3;
        float v = b2[e];
        #pragma unroll
        for (int cg = 0; cg < 10; ++cg) v += sm.scratch[(e*40 + cg*4 + b)*15 + s];
        sm.h2[(b*EMB + e)*15 + s] = v;
    }
    __syncthreads();

    // ---- phase 5a: DFT stats + fc/atan2 -> params ----
    if (t < 24) {
        int b = t & 3, e = t >> 2;
        int pe = b*EMB + e;
        const float* hr = sm.h2 + pe*15;
        float h[15];
        #pragma unroll
        for (int s = 0; s < 15; ++s) h[s] = hr[s];

        float re0 = 0.f;
        #pragma unroll
        for (int s = 0; s < 15; ++s) re0 += h[s];

        float psum = 0.f, fs = 0.f;
        for (int j = 1; j <= 7; ++j) {
            float re = 0.f, im = 0.f;
            int idx = 0;
            #pragma unroll
            for (int s = 0; s < 15; ++s) {
                re = fmaf(h[s], sm.ctab[idx], re);
                im = fmaf(h[s], sm.stab[idx], im);
                idx += j; if (idx >= 15) idx -= 15;
            }
            float pw = re*re + im*im;
            psum += pw;
            fs   += (float)j * pw;
        }
        float f   = fs / (0.3f * psum);
        float a   = 2.f * sqrtf(psum) * (1.f/15.f);
        float off = re0 * (1.f/15.f);

        float v0 = fcb[e*2 + 0], v1 = fcb[e*2 + 1];
        #pragma unroll
        for (int s = 0; s < 15; ++s) {
            v0 = fmaf(h[s], fcw[e*30 + s],      v0);
            v1 = fmaf(h[s], fcw[e*30 + 15 + s], v1);
        }
        float p = atan2f(v1, v0) * (1.f/TPIf);

        sm.scratch[SC_PAR + pe*4 + 0] = f;
        sm.scratch[SC_PAR + pe*4 + 1] = a;
        sm.scratch[SC_PAR + pe*4 + 2] = off;
        sm.scratch[SC_PAR + pe*4 + 3] = p;
    }
    __syncthreads();

    // ---- phase 5b: sinusoid fill ----
    for (int i = t; i < 360; i += NT) {
        int pe = i / 15, s = i - pe*15;
        int id = pe*4;
        float f   = sm.scratch[SC_PAR + id + 0];
        float a   = sm.scratch[SC_PAR + id + 1];
        float off = sm.scratch[SC_PAR + id + 2];
        float p   = sm.scratch[SC_PAR + id + 3];
        float arg = -0.15f + (float)s * (0.3f/14.f);
        sm.sigp[pe*SGROW + 7 + s] = fmaf(a, sinf(TPIf * (f*arg + p)), off);
    }
    __syncthreads();

    // ---- phase 7: deconv1 (6->240), b-pair passes ----
    if (t < 240) {
        const int m = t;
        const float* wgbase = g_dw1p + m*16;
        const float  bias   = db1[m];

        #pragma unroll 1
        for (int bp = 0; bp < 2; ++bp) {
            const float* sp0 = sm.sigp + (2*bp  )*EMB*SGROW;
            const float* sp1 = sm.sigp + (2*bp+1)*EMB*SGROW;
            float acc0[15], acc1[15];
            #pragma unroll
            for (int s = 0; s < 15; ++s) { acc0[s] = 0.f; acc1[s] = 0.f; }

            float wa[16], wb_[16];
            ldw16g(wa, wgbase);
            #pragma unroll 1
            for (int e = 0; e < 6; e += 2) {
                ldw16g(wb_, wgbase + (size_t)(e+1)*3840);
                {
                    float xv[32];
                    ldxv32(xv, sp0 + e*SGROW); conv225(acc0, xv, wa);
                    ldxv32(xv, sp1 + e*SGROW); conv225(acc1, xv, wa);
                }
                if (e+2 < 6) ldw16g(wa, wgbase + (size_t)(e+2)*3840);
                {
                    float xv[32];
                    ldxv32(xv, sp0 + (e+1)*SGROW); conv225(acc0, xv, wb_);
                    ldxv32(xv, sp1 + (e+1)*SGROW); conv225(acc1, xv, wb_);
                }
            }
            float ls0 = 0.f, lq0 = 0.f, ls1 = 0.f, lq1 = 0.f;
            float* h0 = sm.h1 + h1off(2*bp,   m);
            float* h1r= sm.h1 + h1off(2*bp+1, m);
            #pragma unroll
            for (int s = 0; s < 15; ++s) {
                float v0 = acc0[s] + bias; h0[s]  = v0; ls0 += v0; lq0 += v0*v0;
                float v1 = acc1[s] + bias; h1r[s] = v1; ls1 += v1; lq1 += v1*v1;
            }
            h0[15] = 0.f; h1r[15] = 0.f;
            sm.scratch[SC_SUM + (2*bp  )*240 + m] = ls0;
            sm.scratch[SC_SQ  + (2*bp  )*240 + m] = lq0;
            sm.scratch[SC_SUM + (2*bp+1)*240 + m] = ls1;
            sm.scratch[SC_SQ  + (2*bp+1)*240 + m] = lq1;
        }
    }
    __syncthreads();
    if (t < 48) {
        int b = t & 3, g = t >> 2;
        float s_ = 0.f, q_ = 0.f;
        for (int i = 0; i < 20; ++i) {
            s_ += sm.scratch[SC_SUM + b*240 + g*20 + i];
            q_ += sm.scratch[SC_SQ  + b*240 + g*20 + i];
        }
        sm.scratch[SC_R2S + b*12 + g] = s_;
        sm.scratch[SC_R2Q + b*12 + g] = q_;
    }
    __syncthreads();
    if (t < BT) {
        float s_ = 0.f, q_ = 0.f;
        for (int g = 0; g < 12; ++g) {
            s_ += sm.scratch[SC_R2S + t*12 + g];
            q_ += sm.scratch[SC_R2Q + t*12 + g];
        }
        float mn  = s_ * (1.f/3600.f);
        float var = q_ * (1.f/3600.f) - mn*mn;
        sm.mean[t] = mn;
        sm.rstd[t] = rsqrtf(var + 1e-5f);
    }
    __syncthreads();

    // ---- phase 8: LN2 + ELU ----
    for (int i = t; i < 3840; i += NT) {
        int b  = i / 960;
        int rg = i - b*960;
        int row = rg >> 2, g = rg & 3;
        float* hp = sm.h1 + h1off(b, row) + 4*g;
        float4 h = *(float4*)hp;
        float4 w = *(const float4*)(g_dnwp + row*16 + 4*g);
        float4 bb= *(const float4*)(g_dnbp + row*16 + 4*g);
        float mn = sm.mean[b], rs = sm.rstd[b];
        float v;
        v = (h.x-mn)*rs*w.x + bb.x; h.x = (v > 0.f) ? v : (__expf(v)-1.f);
        v = (h.y-mn)*rs*w.y + bb.y; h.y = (v > 0.f) ? v : (__expf(v)-1.f);
        v = (h.z-mn)*rs*w.z + bb.z; h.z = (v > 0.f) ? v : (__expf(v)-1.f);
        v = (h.w-mn)*rs*w.w + bb.w; h.w = (v > 0.f) ? v : (__expf(v)-1.f);
        *(float4*)hp = h;
    }
    __syncthreads();

    // ---- phase 9: deconv2, s=14 only ----
    if (t < 240) {
        int o = t / 5, q = t - o*5;
        int c0 = q * 48;
        const float* wg = g_dw2p + ((size_t)o*240 + c0)*8;
        float acc[4];
        #pragma unroll
        for (int b = 0; b < 4; ++b) acc[b] = 0.f;

        float wA[8], wB[8];
        ldw8g(wA, wg);
        #pragma unroll 1
        for (int ci = 0; ci < 48; ci += 2) {
            ldw8g(wB, wg + (ci+1)*8);
            {
                int c = c0 + ci;
                #pragma unroll
                for (int b = 0; b < 4; ++b) {
                    const float* hr = sm.h1 + h1off(b, c) + 7;
                    #pragma unroll
                    for (int k = 0; k < 8; ++k) acc[b] = fmaf(hr[k], wA[k], acc[b]);
                }
            }
            if (ci+2 < 48) ldw8g(wA, wg + (ci+2)*8);
            {
                int c = c0 + ci + 1;
                #pragma unroll
                for (int b = 0; b < 4; ++b) {
                    const float* hr = sm.h1 + h1off(b, c) + 7;
                    #pragma unroll
                    for (int k = 0; k < 8; ++k) acc[b] = fmaf(hr[k], wB[k], acc[b]);
                }
            }
        }
        #pragma unroll
        for (int b = 0; b < 4; ++b) sm.scratch[t*4 + b] = acc[b];
    }
    __syncthreads();

    if (t < 192) {
        int o = t >> 2, b = t & 3;
        float v = db2[o];
        #pragma unroll
        for (int q = 0; q < 5; ++q) v += sm.scratch[(o*5 + q)*4 + b];
        out[(size_t)(b0 + b)*OUTC + o] = v;
    }
}

extern "C" void kernel_launch(void* const* d_in, const int* in_sizes, int n_in,
                              void* d_out, int out_size)
{
    const float* x   = (const float*)d_in[0];
    const float* w1  = (const float*)d_in[1];
    const float* b1  = (const float*)d_in[2];
    const float* nw1 = (const float*)d_in[3];
    const float* nb1 = (const float*)d_in[4];
    const float* w2  = (const float*)d_in[5];
    const float* b2  = (const float*)d_in[6];
    const float* fcw = (const float*)d_in[7];
    const float* fcb = (const float*)d_in[8];
    const float* dw1 = (const float*)d_in[9];
    const float* db1 = (const float*)d_in[10];
    const float* dnw = (const float*)d_in[11];
    const float* dnb = (const float*)d_in[12];
    const float* dw2 = (const float*)d_in[13];
    const float* db2 = (const float*)d_in[14];
    float* out = (float*)d_out;

    int ntot = NA + N2 + N3 + N4 + N5;
    prep_kernel<<<(ntot + NT - 1)/NT, NT>>>(w1, w2, dw1, dw2, nw1, nb1, dnw, dnb);

    cudaFuncSetAttribute(pae_kernel, cudaFuncAttributeMaxDynamicSharedMemorySize,
                         (int)sizeof(Smem));
    pae_kernel<<<Bsz / BT, NT, sizeof(Smem)>>>(x, b1, b2, fcw, fcb, db1, db2, out);
}

// round 14
// speedup vs baseline: 2.2451x; 2.2451x over previous
#include <cuda_runtime.h>
#include <math.h>

#define TPIf 6.2831853071795864769f

constexpr int Bsz  = 16384;
constexpr int S    = 15;
constexpr int MID  = 240;
constexpr int EMB  = 6;
constexpr int OUTC = 48;
constexpr int BT   = 4;     // samples per CTA
constexpr int NT   = 256;   // threads per CTA

constexpr int XROW   = 36;            // padded x row stride
constexpr int XPANEL = 48*XROW + 4;   // 1732 floats
constexpr int SGROW  = 36;            // sinusoid row stride
constexpr int HSTR   = 3876;          // h1 per-sample stride (mod 32 = 4 -> b skew)

// h1 row offset with cg-deskew: 4*((c/30)&7) breaks cross-cg bank collisions
__device__ __forceinline__ int h1off(int b, int c) {
    return b*HSTR + c*16 + 4*((c/30) & 7);
}

// ---- padded/reindexed weight scratch (filled by prep kernel) ----
__device__ float g_w1p [48*240*16];   // [c][m][16]
__device__ float g_w2p [6*240*16];    // [e][c][16]
__device__ float g_dw1p[6*240*16];    // [e][m][16]
__device__ float g_dw2p[48*240*8];    // [o][c][8]  (taps 0..7)
__device__ float g_nw1p[240*16];      // padded LN params (col15 = 0)
__device__ float g_nb1p[240*16];
__device__ float g_dnwp[240*16];
__device__ float g_dnbp[240*16];

constexpr int N1 = 48*240*16, N2 = 6*240*16, N3 = 6*240*16, N4 = 48*240*8;
constexpr int N5 = 4*240*16;

__global__ void prep_kernel(const float* __restrict__ w1, const float* __restrict__ w2,
                            const float* __restrict__ dw1, const float* __restrict__ dw2,
                            const float* __restrict__ nw1, const float* __restrict__ nb1,
                            const float* __restrict__ dnw, const float* __restrict__ dnb)
{
    int i = blockIdx.x*blockDim.x + threadIdx.x;
    if (i < N1) {                                   // g_w1p[c][m][16]
        int k = i & 15, cm = i >> 4;
        int c = cm / 240, m = cm % 240;
        g_w1p[i] = (k < 15) ? w1[(m*48 + c)*15 + k] : 0.f;
    } else if (i < N1+N2) {                         // g_w2p[e][c][16]
        int j = i - N1; int k = j & 15, ec = j >> 4;
        g_w2p[j] = (k < 15) ? w2[ec*15 + k] : 0.f;
    } else if (i < N1+N2+N3) {                      // g_dw1p[e][m][16]
        int j = i - N1 - N2; int k = j & 15, em = j >> 4;
        int e = em / 240, m = em % 240;
        g_dw1p[j] = (k < 15) ? dw1[(m*6 + e)*15 + k] : 0.f;
    } else if (i < N1+N2+N3+N4) {                   // g_dw2p[o][c][8]
        int j = i - N1 - N2 - N3; int k = j & 7, oc = j >> 3;
        g_dw2p[j] = dw2[oc*15 + k];
    } else if (i < N1+N2+N3+N4+N5) {                // LN params, padded
        int j = i - N1 - N2 - N3 - N4;
        int tab = j / 3840, idx = j % 3840;
        int row = idx >> 4, col = idx & 15;
        float v = 0.f;
        if (col < 15) {
            const float* src = (tab == 0) ? nw1 : (tab == 1) ? nb1
                             : (tab == 2) ? dnw : dnb;
            v = src[row*15 + col];
        }
        float* dst = (tab == 0) ? g_nw1p : (tab == 1) ? g_nb1p
                   : (tab == 2) ? g_dnwp : g_dnbp;
        dst[idx] = v;
    }
}

struct Smem {
    float xpad[BT*XPANEL];       // 6928
    float h1[BT*HSTR];           // 15504: [b] skewed, rows c*16 + deskew
    float h2[BT*EMB*S];          // 360
    float sigp[BT*EMB*SGROW];    // 864
    float red2[192*15];          // 2880 : scratch (conv2 partials + LN stage)
    float redsum[4][240];        // 960
    float redsq[4][240];         // 960
    float ctab[15], stab[15];
    float mean[BT], rstd[BT];
};

// dense regular 15-tap x 15-out conv block (225 FMAs) — proven-fast codegen
__device__ __forceinline__ void conv225(float (&acc)[15], const float (&xv)[32],
                                        const float (&w)[16])
{
    #pragma unroll
    for (int k = 0; k < 15; ++k) {
        #pragma unroll
        for (int s = 0; s < 15; ++s)
            acc[s] = fmaf(w[k], xv[k+s], acc[s]);
    }
}

__device__ __forceinline__ void ldxv32(float (&xv)[32], const float* p) {
    const float4* q = (const float4*)p;
    #pragma unroll
    for (int j = 0; j < 8; ++j) {
        float4 v = q[j];
        xv[4*j+0]=v.x; xv[4*j+1]=v.y; xv[4*j+2]=v.z; xv[4*j+3]=v.w;
    }
}

__device__ __forceinline__ void ldw16g(float (&w)[16], const float* __restrict__ p) {
    const float4* q = (const float4*)p;
    #pragma unroll
    for (int j = 0; j < 4; ++j) {
        float4 v = __ldg(q + j);
        w[4*j+0]=v.x; w[4*j+1]=v.y; w[4*j+2]=v.z; w[4*j+3]=v.w;
    }
}

__device__ __forceinline__ void ldw8g(float (&w)[8], const float* __restrict__ p) {
    const float4* q = (const float4*)p;
    #pragma unroll
    for (int j = 0; j < 2; ++j) {
        float4 v = __ldg(q + j);
        w[4*j+0]=v.x; w[4*j+1]=v.y; w[4*j+2]=v.z; w[4*j+3]=v.w;
    }
}

__global__ void __launch_bounds__(NT, 2)
pae_kernel(const float* __restrict__ x,
           const float* __restrict__ b1,
           const float* __restrict__ b2,
           const float* __restrict__ fcw, const float* __restrict__ fcb,
           const float* __restrict__ db1,
           const float* __restrict__ db2,
           float* __restrict__ out)
{
    extern __shared__ float sm_raw[];
    Smem& sm = *reinterpret_cast<Smem*>(sm_raw);
    const int t  = threadIdx.x;
    const int b0 = blockIdx.x * BT;

    // ---------------- phase 0: zero pads, twiddle tables, load x ----------------
    for (int i = t; i < BT*XPANEL; i += NT) sm.xpad[i] = 0.f;
    for (int i = t; i < BT*EMB*SGROW; i += NT) sm.sigp[i] = 0.f;
    if (t < 15) {
        float s_, c_;
        sincosf(TPIf * (float)t / 15.f, &s_, &c_);
        sm.ctab[t] = c_;
        sm.stab[t] = -s_;
    }
    __syncthreads();

    for (int i = t; i < BT*720; i += NT) {
        int b = i / 720, r = i - b*720;
        int c = r / 15,  s = r - c*15;
        sm.xpad[b*XPANEL + c*XROW + 7 + s] = x[(size_t)(b0+b)*720 + r];
    }
    __syncthreads();

    // ---------------- phase 1: conv1 (48->240) — thread = m, b-pair passes ----------------
    if (t < 240) {
        const int m = t;
        const float* wgbase = g_w1p + m*16;          // [c][m][16]
        const float  bias   = b1[m];

        #pragma unroll 1
        for (int bp = 0; bp < 2; ++bp) {
            const float* xr0 = sm.xpad + (2*bp  )*XPANEL;
            const float* xr1 = sm.xpad + (2*bp+1)*XPANEL;
            float acc0[15], acc1[15];
            #pragma unroll
            for (int s = 0; s < 15; ++s) { acc0[s] = 0.f; acc1[s] = 0.f; }

            float wa[16], wb_[16];
            ldw16g(wa, wgbase);                       // c = 0
            #pragma unroll 1
            for (int c = 0; c < 48; c += 2) {
                ldw16g(wb_, wgbase + (size_t)(c+1)*3840);
                {
                    float xv[32];
                    ldxv32(xv, xr0 + c*XROW); conv225(acc0, xv, wa);
                    ldxv32(xv, xr1 + c*XROW); conv225(acc1, xv, wa);
                }
                if (c+2 < 48) ldw16g(wa, wgbase + (size_t)(c+2)*3840);
                {
                    float xv[32];
                    ldxv32(xv, xr0 + (c+1)*XROW); conv225(acc0, xv, wb_);
                    ldxv32(xv, xr1 + (c+1)*XROW); conv225(acc1, xv, wb_);
                }
            }
            float ls0 = 0.f, lq0 = 0.f, ls1 = 0.f, lq1 = 0.f;
            float* h0 = sm.h1 + h1off(2*bp,   m);
            float* h1r= sm.h1 + h1off(2*bp+1, m);
            #pragma unroll
            for (int s = 0; s < 15; ++s) {
                float v0 = acc0[s] + bias; h0[s]  = v0; ls0 += v0; lq0 += v0*v0;
                float v1 = acc1[s] + bias; h1r[s] = v1; ls1 += v1; lq1 += v1*v1;
            }
            h0[15] = 0.f; h1r[15] = 0.f;              // pad col (NaN safety)
            sm.redsum[2*bp  ][m] = ls0; sm.redsq[2*bp  ][m] = lq0;
            sm.redsum[2*bp+1][m] = ls1; sm.redsq[2*bp+1][m] = lq1;
        }
    }
    __syncthreads();
    if (t < 48) {
        int b = t & 3, g = t >> 2;                    // g in 0..11, 20 rows each
        float s_ = 0.f, q_ = 0.f;
        for (int i = 0; i < 20; ++i) { s_ += sm.redsum[b][g*20+i]; q_ += sm.redsq[b][g*20+i]; }
        sm.red2[b*12 + g] = s_;
        sm.red2[64 + b*12 + g] = q_;
    }
    __syncthreads();
    if (t < BT) {
        float s_ = 0.f, q_ = 0.f;
        for (int g = 0; g < 12; ++g) { s_ += sm.red2[t*12+g]; q_ += sm.red2[64+t*12+g]; }
        float mn  = s_ * (1.f/3600.f);
        float var = q_ * (1.f/3600.f) - mn*mn;
        sm.mean[t] = mn;
        sm.rstd[t] = rsqrtf(var + 1e-5f);
    }
    __syncthreads();

    // ---------------- phase 2: LN1 + ELU (vectorized, pad col stays 0) ----------------
    for (int i = t; i < 3840; i += NT) {
        int b  = i / 960;
        int rg = i - b*960;
        int row = rg >> 2, g = rg & 3;
        float* hp = sm.h1 + h1off(b, row) + 4*g;
        float4 h = *(float4*)hp;
        float4 w = *(const float4*)(g_nw1p + row*16 + 4*g);
        float4 bb= *(const float4*)(g_nb1p + row*16 + 4*g);
        float mn = sm.mean[b], rs = sm.rstd[b];
        float v;
        v = (h.x-mn)*rs*w.x + bb.x; h.x = (v > 0.f) ? v : (__expf(v)-1.f);
        v = (h.y-mn)*rs*w.y + bb.y; h.y = (v > 0.f) ? v : (__expf(v)-1.f);
        v = (h.z-mn)*rs*w.z + bb.z; h.z = (v > 0.f) ? v : (__expf(v)-1.f);
        v = (h.w-mn)*rs*w.w + bb.w; h.w = (v > 0.f) ? v : (__expf(v)-1.f);
        *(float4*)hp = h;
    }
    __syncthreads();

    // ---------------- phase 3: conv2 (240->6) ----------------
    if (t < 192) {
        int b = t & 3, cg = (t >> 2) & 7, e = t >> 5;
        float acc[15];
        #pragma unroll
        for (int s = 0; s < 15; ++s) acc[s] = 0.f;
        const float* hbase = sm.h1 + b*HSTR + cg*30*16 + 4*cg;   // deskewed base
        const float* wg = g_w2p + ((size_t)e*240 + cg*30)*16;

        float wa[16], wb_[16];
        ldw16g(wa, wg);
        #pragma unroll 1
        for (int ci = 0; ci < 30; ci += 2) {
            ldw16g(wb_, wg + (ci+1)*16);
            {
                float xv[32];
                #pragma unroll
                for (int j = 0; j < 7; ++j)  xv[j] = 0.f;
                #pragma unroll
                for (int j = 23; j < 32; ++j) xv[j] = 0.f;
                const float4* q = (const float4*)(hbase + ci*16);
                #pragma unroll
                for (int j = 0; j < 4; ++j) {
                    float4 v = q[j];
                    xv[7+4*j]=v.x; xv[8+4*j]=v.y; xv[9+4*j]=v.z; xv[10+4*j]=v.w;
                }
                conv225(acc, xv, wa);
            }
            if (ci+2 < 30) ldw16g(wa, wg + (ci+2)*16);
            {
                float xv[32];
                #pragma unroll
                for (int j = 0; j < 7; ++j)  xv[j] = 0.f;
                #pragma unroll
                for (int j = 23; j < 32; ++j) xv[j] = 0.f;
                const float4* q = (const float4*)(hbase + (ci+1)*16);
                #pragma unroll
                for (int j = 0; j < 4; ++j) {
                    float4 v = q[j];
                    xv[7+4*j]=v.x; xv[8+4*j]=v.y; xv[9+4*j]=v.z; xv[10+4*j]=v.w;
                }
                conv225(acc, xv, wb_);
            }
        }
        #pragma unroll
        for (int s = 0; s < 15; ++s) sm.red2[t*15 + s] = acc[s];
    }
    __syncthreads();
    for (int i = t; i < 360; i += NT) {
        int be = i / 15, s = i - be*15;
        int e = be >> 2, b = be & 3;
        float v = b2[e];
        #pragma unroll
        for (int cg = 0; cg < 8; ++cg) v += sm.red2[(e*32 + cg*4 + b)*15 + s];
        sm.h2[(b*EMB + e)*15 + s] = v;
    }
    __syncthreads();

    // ---------------- phase 5: DFT stats + fc/atan2 + sinusoid ----------------
    if (t < 24) {
        int b = t & 3, e = t >> 2;
        const float* hr = sm.h2 + (b*EMB + e)*15;
        float h[15];
        #pragma unroll
        for (int s = 0; s < 15; ++s) h[s] = hr[s];

        float re0 = 0.f;
        #pragma unroll
        for (int s = 0; s < 15; ++s) re0 += h[s];

        float psum = 0.f, fs = 0.f;
        for (int j = 1; j <= 7; ++j) {
            float re = 0.f, im = 0.f;
            int idx = 0;
            #pragma unroll
            for (int s = 0; s < 15; ++s) {
                re = fmaf(h[s], sm.ctab[idx], re);
                im = fmaf(h[s], sm.stab[idx], im);
                idx += j; if (idx >= 15) idx -= 15;
            }
            float pw = re*re + im*im;
            psum += pw;
            fs   += (float)j * pw;
        }
        float f   = fs / (0.3f * psum);
        float a   = 2.f * sqrtf(psum) * (1.f/15.f);
        float off = re0 * (1.f/15.f);

        float v0 = fcb[e*2 + 0], v1 = fcb[e*2 + 1];
        #pragma unroll
        for (int s = 0; s < 15; ++s) {
            v0 = fmaf(h[s], fcw[e*30 + s],      v0);
            v1 = fmaf(h[s], fcw[e*30 + 15 + s], v1);
        }
        float p = atan2f(v1, v0) * (1.f/TPIf);

        float* srow = sm.sigp + (b*EMB + e)*SGROW;
        #pragma unroll
        for (int s = 0; s < 15; ++s) {
            float arg = -0.15f + (float)s * (0.3f/14.f);
            srow[7 + s] = fmaf(a, sinf(TPIf * (f*arg + p)), off);
        }
    }
    __syncthreads();

    // ---------------- phase 7: deconv1 (6->240) — thread = m, b-pair passes ----------------
    if (t < 240) {
        const int m = t;
        const float* wgbase = g_dw1p + m*16;          // [e][m][16]
        const float  bias   = db1[m];

        #pragma unroll 1
        for (int bp = 0; bp < 2; ++bp) {
            const float* sp0 = sm.sigp + (2*bp  )*EMB*SGROW;
            const float* sp1 = sm.sigp + (2*bp+1)*EMB*SGROW;
            float acc0[15], acc1[15];
            #pragma unroll
            for (int s = 0; s < 15; ++s) { acc0[s] = 0.f; acc1[s] = 0.f; }

            float wa[16], wb_[16];
            ldw16g(wa, wgbase);                        // e = 0
            #pragma unroll 1
            for (int e = 0; e < 6; e += 2) {
                ldw16g(wb_, wgbase + (size_t)(e+1)*3840);
                {
                    float xv[32];
                    ldxv32(xv, sp0 + e*SGROW); conv225(acc0, xv, wa);
                    ldxv32(xv, sp1 + e*SGROW); conv225(acc1, xv, wa);
                }
                if (e+2 < 6) ldw16g(wa, wgbase + (size_t)(e+2)*3840);
                {
                    float xv[32];
                    ldxv32(xv, sp0 + (e+1)*SGROW); conv225(acc0, xv, wb_);
                    ldxv32(xv, sp1 + (e+1)*SGROW); conv225(acc1, xv, wb_);
                }
            }
            float ls0 = 0.f, lq0 = 0.f, ls1 = 0.f, lq1 = 0.f;
            float* h0 = sm.h1 + h1off(2*bp,   m);
            float* h1r= sm.h1 + h1off(2*bp+1, m);
            #pragma unroll
            for (int s = 0; s < 15; ++s) {
                float v0 = acc0[s] + bias; h0[s]  = v0; ls0 += v0; lq0 += v0*v0;
                float v1 = acc1[s] + bias; h1r[s] = v1; ls1 += v1; lq1 += v1*v1;
            }
            h0[15] = 0.f; h1r[15] = 0.f;
            sm.redsum[2*bp  ][m] = ls0; sm.redsq[2*bp  ][m] = lq0;
            sm.redsum[2*bp+1][m] = ls1; sm.redsq[2*bp+1][m] = lq1;
        }
    }
    __syncthreads();
    if (t < 48) {
        int b = t & 3, g = t >> 2;
        float s_ = 0.f, q_ = 0.f;
        for (int i = 0; i < 20; ++i) { s_ += sm.redsum[b][g*20+i]; q_ += sm.redsq[b][g*20+i]; }
        sm.red2[b*12 + g] = s_;
        sm.red2[64 + b*12 + g] = q_;
    }
    __syncthreads();
    if (t < BT) {
        float s_ = 0.f, q_ = 0.f;
        for (int g = 0; g < 12; ++g) { s_ += sm.red2[t*12+g]; q_ += sm.red2[64+t*12+g]; }
        float mn  = s_ * (1.f/3600.f);
        float var = q_ * (1.f/3600.f) - mn*mn;
        sm.mean[t] = mn;
        sm.rstd[t] = rsqrtf(var + 1e-5f);
    }
    __syncthreads();

    // ---------------- phase 8: LN2 + ELU (vectorized) ----------------
    for (int i = t; i < 3840; i += NT) {
        int b  = i / 960;
        int rg = i - b*960;
        int row = rg >> 2, g = rg & 3;
        float* hp = sm.h1 + h1off(b, row) + 4*g;
        float4 h = *(float4*)hp;
        float4 w = *(const float4*)(g_dnwp + row*16 + 4*g);
        float4 bb= *(const float4*)(g_dnbp + row*16 + 4*g);
        float mn = sm.mean[b], rs = sm.rstd[b];
        float v;
        v = (h.x-mn)*rs*w.x + bb.x; h.x = (v > 0.f) ? v : (__expf(v)-1.f);
        v = (h.y-mn)*rs*w.y + bb.y; h.y = (v > 0.f) ? v : (__expf(v)-1.f);
        v = (h.z-mn)*rs*w.z + bb.z; h.z = (v > 0.f) ? v : (__expf(v)-1.f);
        v = (h.w-mn)*rs*w.w + bb.w; h.w = (v > 0.f) ? v : (__expf(v)-1.f);
        *(float4*)hp = h;
    }
    __syncthreads();

    // ---------------- phase 9: deconv2, only s=14 (k 0..7) ----------------
    if (t < 192) {
        int o = t >> 2, q = t & 3;
        int c0 = q * 60;
        const float* wg = g_dw2p + ((size_t)o*240 + c0)*8;
        float acc[4];
        #pragma unroll
        for (int b = 0; b < 4; ++b) acc[b] = 0.f;

        float wA[8], wB[8];
        ldw8g(wA, wg);
        #pragma unroll 1
        for (int ci = 0; ci < 60; ci += 2) {
            ldw8g(wB, wg + (ci+1)*8);
            {
                int c = c0 + ci;
                #pragma unroll
                for (int b = 0; b < 4; ++b) {
                    const float* hr = sm.h1 + h1off(b, c) + 7;
                    #pragma unroll
                    for (int k = 0; k < 8; ++k) acc[b] = fmaf(hr[k], wA[k], acc[b]);
                }
            }
            if (ci+2 < 60) ldw8g(wA, wg + (ci+2)*8);
            {
                int c = c0 + ci + 1;
                #pragma unroll
                for (int b = 0; b < 4; ++b) {
                    const float* hr = sm.h1 + h1off(b, c) + 7;
                    #pragma unroll
                    for (int k = 0; k < 8; ++k) acc[b] = fmaf(hr[k], wB[k], acc[b]);
                }
            }
        }
        #pragma unroll
        for (int b = 0; b < 4; ++b) sm.red2[(o*4 + q)*4 + b] = acc[b];
    }
    __syncthreads();

    if (t < 192) {
        int o = t >> 2, b = t & 3;
        float v = db2[o];
        #pragma unroll
        for (int q = 0; q < 4; ++q) v += sm.red2[(o*4 + q)*4 + b];
        out[(size_t)(b0 + b)*OUTC + o] = v;
    }
}

extern "C" void kernel_launch(void* const* d_in, const int* in_sizes, int n_in,
                              void* d_out, int out_size)
{
    const float* x   = (const float*)d_in[0];
    const float* w1  = (const float*)d_in[1];
    const float* b1  = (const float*)d_in[2];
    const float* nw1 = (const float*)d_in[3];
    const float* nb1 = (const float*)d_in[4];
    const float* w2  = (const float*)d_in[5];
    const float* b2  = (const float*)d_in[6];
    const float* fcw = (const float*)d_in[7];
    const float* fcb = (const float*)d_in[8];
    const float* dw1 = (const float*)d_in[9];
    const float* db1 = (const float*)d_in[10];
    const float* dnw = (const float*)d_in[11];
    const float* dnb = (const float*)d_in[12];
    const float* dw2 = (const float*)d_in[13];
    const float* db2 = (const float*)d_in[14];
    float* out = (float*)d_out;

    int ntot = N1 + N2 + N3 + N4 + N5;
    prep_kernel<<<(ntot + NT - 1)/NT, NT>>>(w1, w2, dw1, dw2, nw1, nb1, dnw, dnb);

    cudaFuncSetAttribute(pae_kernel, cudaFuncAttributeMaxDynamicSharedMemorySize,
                         (int)sizeof(Smem));
    pae_kernel<<<Bsz / BT, NT, sizeof(Smem)>>>(x, b1, b2, fcw, fcb, db1, db2, out);
}